// round 6
// baseline (speedup 1.0000x reference)
#include <cuda_runtime.h>
#include <cstddef>

#define Mn   2048
#define LLn  64
#define Pp   4
#define Ssn  2
#define RPB  16
#define NTHR 256
#define NBLK (Mn/RPB)

// smem floats: wbuf[32768] | hA[2048] | zS[8192] | ids[96]
#define OFF_HA 32768
#define OFF_ZS (32768+2048)
#define OFF_ID (32768+2048+8192)
#define SMEMB  ((OFF_ID+96)*4)   /* 172800 B */

__device__ float g_EWm[(size_t)LLn * Mn * 512];
__device__ float g_EWs[(size_t)LLn * Mn * 512];
__device__ float g_c0[128];
__device__ float g_z1b[512];
// pair-packed weights: [P(64)][t(256)][4] = {W[2P][2t],W[2P+1][2t],W[2P][2t+1],W[2P+1][2t+1]}
__device__ float g_Ump[65536];
__device__ float g_Usp[65536];
__device__ float g_Wmp[65536];
__device__ float g_Wsp[65536];

typedef unsigned long long u64t;

__device__ __forceinline__ float2 u2f(u64t u){ float2 v; asm("mov.b64 {%0,%1},%2;":"=f"(v.x),"=f"(v.y):"l"(u)); return v; }
__device__ __forceinline__ void fma2(u64t&a, u64t x, u64t w){ asm("fma.rn.f32x2 %0,%1,%2,%0;":"+l"(a):"l"(x),"l"(w)); }
__device__ __forceinline__ float redu(u64t a){ float2 v=u2f(a); return v.x+v.y; }

__device__ __forceinline__ void cpa16(float* sdst, const float* gsrc){
  unsigned s=(unsigned)__cvta_generic_to_shared(sdst);
  asm volatile("cp.async.cg.shared.global [%0],[%1],16;"::"r"(s),"l"(gsrc));
}
__device__ __forceinline__ void cpcommit(){ asm volatile("cp.async.commit_group;":::"memory"); }
__device__ __forceinline__ void cpwait1(){ asm volatile("cp.async.wait_group 1;":::"memory"); }
__device__ __forceinline__ void cpwait0(){ asm volatile("cp.async.wait_group 0;":::"memory"); }

__device__ __forceinline__ float sigf(float x){ return 1.f/(1.f+__expf(-x)); }
__device__ __forceinline__ float tfast(float x){
  x = fminf(fmaxf(x,-15.f),15.f);
  float t = __expf(2.f*x);
  return (t-1.f)/(t+1.f);
}

// acc[r][c]: u64 {sum even k, sum odd k} for column 2*tid+c of z[r], r = all 16 rows.
// Wp pair-packed. xs = hA [16][128] in smem. 4 k-tiles of 32, double-buffered.
__device__ __forceinline__ void gemm_full(u64t acc[RPB][2], const float* __restrict__ Wp,
    const float* xs, float* wbuf, int tid)
{
  #pragma unroll
  for(int i=0;i<16;i++) cpa16(wbuf + 4*(tid+256*i), Wp + 4*(tid+256*i));
  cpcommit();
  #pragma unroll 1
  for(int kt=0;kt<4;kt++){
    if(kt<3){
      const float* src = Wp + (kt+1)*16384;
      float* dst = wbuf + ((kt+1)&1)*16384;
      #pragma unroll
      for(int i=0;i<16;i++) cpa16(dst + 4*(tid+256*i), src + 4*(tid+256*i));
      cpcommit(); cpwait1();
    } else {
      cpwait0();
    }
    __syncthreads();
    const float* wb = wbuf + (kt&1)*16384;
    #pragma unroll
    for(int q=0;q<8;q++){
      // pairs P=2q, 2q+1 of this tile (k = 4q..4q+3 local)
      const ulonglong2* wp = (const ulonglong2*)(wb + (2*q*256 + tid)*4);
      ulonglong2 w0 = wp[0];     // P  : {col 2t, col 2t+1}
      ulonglong2 w1 = wp[256];   // P+1: {col 2t, col 2t+1}
      const float* xq = xs + kt*32 + q*4;
      #pragma unroll
      for(int r=0;r<RPB;r++){
        ulonglong2 xv = *(const ulonglong2*)(xq + r*128);  // broadcast {h[4q..4q+3]}
        fma2(acc[r][0], xv.x, w0.x);
        fma2(acc[r][1], xv.x, w0.y);
        fma2(acc[r][0], xv.y, w1.x);
        fma2(acc[r][1], xv.y, w1.y);
      }
    }
    __syncthreads();
  }
}

__device__ __forceinline__ void zero_acc(u64t acc[RPB][2]){
  #pragma unroll
  for(int r=0;r<RPB;r++){ acc[r][0]=0ull; acc[r][1]=0ull; }
}

// cell phase: thread owns rows 4*rgrp..+3, dims d0,d0+1 (gate-aligned view of zS).
__device__ __forceinline__ void cell_phase(const float* zS, float* hA, float2 cst[4], int rgrp, int d0){
  #pragma unroll
  for(int rr=0;rr<4;rr++){
    int r=4*rgrp+rr;
    const float* zr = zS + r*512 + d0;
    float2 zi=*(const float2*)(zr),     zf=*(const float2*)(zr+128);
    float2 zg=*(const float2*)(zr+256), zo=*(const float2*)(zr+384);
    float2& c=cst[rr];
    c.x = sigf(zf.x)*c.x + sigf(zi.x)*tfast(zg.x);
    c.y = sigf(zf.y)*c.y + sigf(zi.y)*tfast(zg.y);
    float2 h;
    h.x = sigf(zo.x)*tfast(c.x);
    h.y = sigf(zo.y)*tfast(c.y);
    *(float2*)(hA + r*128 + d0) = h;
  }
}

__global__ void __launch_bounds__(NTHR,1) layer_kernel(int l, float* __restrict__ emb,
  const int* __restrict__ prop, const int* __restrict__ sup,
  const float* __restrict__ bm, const float* __restrict__ bs)
{
  extern __shared__ float smx[];
  float* wbuf = smx;
  float* hA   = smx + OFF_HA;
  float* zS   = smx + OFF_ZS;
  int*   ids  = (int*)(smx + OFF_ID);
  const int tid=threadIdx.x;
  const int rgrp=tid>>6, d0=2*(tid&63);
  const int c2 = 2*tid;                       // z-column base this thread owns
  const int lrow0 = blockIdx.x*RPB;
  const int base  = l*Mn + lrow0;

  if(tid<RPB*Pp) ids[tid] = prop[lrow0*Pp + tid];
  else if(tid<RPB*Pp+RPB*Ssn) ids[tid] = sup[lrow0*Ssn + (tid-RPB*Pp)];
  __syncthreads();

  u64t acc[RPB][2];
  float2 zlast[RPB];
  float2 cst[4];

  // ---- member t=1: z = E_Wm[pid0] + z1b ; c_prev = c0
  {
    float2 zb = *(const float2*)(g_z1b + c2);
    #pragma unroll
    for(int r=0;r<RPB;r++){
      float2 e = *(const float2*)(g_EWm + (size_t)ids[r*Pp]*512 + c2);
      *(float2*)(zS + r*512 + c2) = make_float2(e.x+zb.x, e.y+zb.y);
    }
  }
  __syncthreads();
  {
    float2 c0v = *(const float2*)(g_c0 + d0);
    #pragma unroll
    for(int rr=0;rr<4;rr++) cst[rr]=c0v;
  }
  cell_phase(zS, hA, cst, rgrp, d0);
  __syncthreads();

  // ---- member t=2..4: z = E_Wm[pid_{t-1}] + h @ Um
  #pragma unroll 1
  for(int t=2;t<=4;t++){
    zero_acc(acc);
    gemm_full(acc, g_Ump, hA, wbuf, tid);
    #pragma unroll
    for(int r=0;r<RPB;r++){
      float2 e = *(const float2*)(g_EWm + (size_t)ids[r*Pp + (t-1)]*512 + c2);
      *(float2*)(zS + r*512 + c2) = make_float2(redu(acc[r][0])+e.x, redu(acc[r][1])+e.y);
    }
    __syncthreads();
    cell_phase(zS, hA, cst, rgrp, d0);
    __syncthreads();
  }
  // hA == h_m

  // ---- zlast = b_s + h_m @ Ws  (kept in registers)
  {
    float2 bsv = *(const float2*)(bs + c2);
    zero_acc(acc);
    gemm_full(acc, g_Wsp, hA, wbuf, tid);
    #pragma unroll
    for(int r=0;r<RPB;r++)
      zlast[r] = make_float2(redu(acc[r][0])+bsv.x, redu(acc[r][1])+bsv.y);
  }

  // ---- super t=0: z = E_Ws[sid0], zero state
  #pragma unroll
  for(int r=0;r<RPB;r++){
    float2 e = *(const float2*)(g_EWs + (size_t)ids[RPB*Pp + r*Ssn]*512 + c2);
    *(float2*)(zS + r*512 + c2) = e;
  }
  __syncthreads();
  #pragma unroll
  for(int rr=0;rr<4;rr++) cst[rr]=make_float2(0.f,0.f);
  cell_phase(zS, hA, cst, rgrp, d0);
  __syncthreads();

  // ---- super t=1: z = E_Ws[sid1] + h @ Us
  zero_acc(acc);
  gemm_full(acc, g_Usp, hA, wbuf, tid);
  #pragma unroll
  for(int r=0;r<RPB;r++){
    float2 e = *(const float2*)(g_EWs + (size_t)ids[RPB*Pp + r*Ssn + 1]*512 + c2);
    *(float2*)(zS + r*512 + c2) = make_float2(redu(acc[r][0])+e.x, redu(acc[r][1])+e.y);
  }
  __syncthreads();
  cell_phase(zS, hA, cst, rgrp, d0);
  __syncthreads();

  // ---- super t=2: z = zlast + h @ Us -> h_s
  zero_acc(acc);
  gemm_full(acc, g_Usp, hA, wbuf, tid);
  #pragma unroll
  for(int r=0;r<RPB;r++)
    *(float2*)(zS + r*512 + c2) = make_float2(redu(acc[r][0])+zlast[r].x, redu(acc[r][1])+zlast[r].y);
  __syncthreads();
  cell_phase(zS, hA, cst, rgrp, d0);
  __syncthreads();

  // ---- write emb rows
  {
    float4* dst=(float4*)(emb + (size_t)base*128);
    const float4* src=(const float4*)hA;
    dst[tid]     = src[tid];
    dst[tid+256] = src[tid+256];
  }

  // ---- produce z-tables for this layer's rows
  {
    float2 bmv = *(const float2*)(bm + c2);
    zero_acc(acc);
    gemm_full(acc, g_Wmp, hA, wbuf, tid);
    #pragma unroll
    for(int r=0;r<RPB;r++)
      *(float2*)(g_EWm + (size_t)(base+r)*512 + c2) = make_float2(redu(acc[r][0])+bmv.x, redu(acc[r][1])+bmv.y);
  }
  {
    float2 bsv = *(const float2*)(bs + c2);
    zero_acc(acc);
    gemm_full(acc, g_Wsp, hA, wbuf, tid);
    #pragma unroll
    for(int r=0;r<RPB;r++)
      *(float2*)(g_EWs + (size_t)(base+r)*512 + c2) = make_float2(redu(acc[r][0])+bsv.x, redu(acc[r][1])+bsv.y);
  }
}

__global__ void __launch_bounds__(NTHR,1) layer0_kernel(float* __restrict__ emb,
  const int* __restrict__ names, const float* __restrict__ btab,
  const float* __restrict__ bm, const float* __restrict__ bs)
{
  extern __shared__ float smx[];
  float* wbuf=smx; float* hA=smx+OFF_HA;
  const int tid=threadIdx.x;
  const int c2 = 2*tid;
  const int row0 = blockIdx.x*RPB;

  for(int i=tid;i<RPB*128;i+=NTHR){
    int r=i>>7, k=i&127;
    float v = btab[names[row0+r]*128 + k];
    hA[i]=v;
    emb[(size_t)(row0+r)*128 + k]=v;
  }
  __syncthreads();

  u64t acc[RPB][2];
  {
    float2 bmv = *(const float2*)(bm + c2);
    zero_acc(acc);
    gemm_full(acc, g_Wmp, hA, wbuf, tid);
    #pragma unroll
    for(int r=0;r<RPB;r++)
      *(float2*)(g_EWm + (size_t)(row0+r)*512 + c2) = make_float2(redu(acc[r][0])+bmv.x, redu(acc[r][1])+bmv.y);
  }
  {
    float2 bsv = *(const float2*)(bs + c2);
    zero_acc(acc);
    gemm_full(acc, g_Wsp, hA, wbuf, tid);
    #pragma unroll
    for(int r=0;r<RPB;r++)
      *(float2*)(g_EWs + (size_t)(row0+r)*512 + c2) = make_float2(redu(acc[r][0])+bsv.x, redu(acc[r][1])+bsv.y);
  }
}

// pre-shuffle [128,512] weight into pair-packed layout
__global__ void shuf_kernel(float* __restrict__ dst, const float* __restrict__ src){
  int i = blockIdx.x*256 + threadIdx.x;  // 0..16383 = P*256 + t
  int P = i>>8, t = i&255;
  float4 v;
  v.x = src[(2*P  )*512 + 2*t  ];
  v.y = src[(2*P+1)*512 + 2*t  ];
  v.z = src[(2*P  )*512 + 2*t+1];
  v.w = src[(2*P+1)*512 + 2*t+1];
  ((float4*)dst)[i] = v;
}

// One-shot constants: z0 = em@Wm + bm -> c0, h0 -> z1b = h0@Um
__global__ void init_kernel(const float* __restrict__ em, const float* __restrict__ Wm,
                            const float* __restrict__ Um, const float* __restrict__ bm)
{
  __shared__ float z0[512]; __shared__ float h0[128]; __shared__ float ems[128];
  int t=threadIdx.x;
  if(t<128) ems[t]=em[t];
  __syncthreads();
  float s=bm[t];
  for(int k=0;k<128;k++) s += ems[k]*Wm[k*512+t];
  z0[t]=s;
  __syncthreads();
  if(t<128){
    float zi=z0[t], zg=z0[256+t], zo=z0[384+t];
    float c = (1.f/(1.f+expf(-zi)))*tanhf(zg);
    g_c0[t]=c;
    h0[t]=(1.f/(1.f+expf(-zo)))*tanhf(c);
  }
  __syncthreads();
  float s2=0.f;
  for(int k=0;k<128;k++) s2 += h0[k]*Um[k*512+t];
  g_z1b[t]=s2;
}

extern "C" void kernel_launch(void* const* d_in, const int* in_sizes, int n_in,
                              void* d_out, int out_size)
{
  const int*   names=(const int*)d_in[0];
  const int*   prop =(const int*)d_in[1];
  const int*   sup  =(const int*)d_in[2];
  const float* btab =(const float*)d_in[3];
  const float* Wm   =(const float*)d_in[4];
  const float* Um   =(const float*)d_in[5];
  const float* bm   =(const float*)d_in[6];
  const float* Ws   =(const float*)d_in[7];
  const float* Us   =(const float*)d_in[8];
  const float* bs   =(const float*)d_in[9];
  const float* em   =(const float*)d_in[10];
  float* emb=(float*)d_out;

  cudaFuncSetAttribute(layer_kernel,  cudaFuncAttributeMaxDynamicSharedMemorySize, SMEMB);
  cudaFuncSetAttribute(layer0_kernel, cudaFuncAttributeMaxDynamicSharedMemorySize, SMEMB);

  float *dUmp, *dUsp, *dWmp, *dWsp;
  cudaGetSymbolAddress((void**)&dUmp, g_Ump);
  cudaGetSymbolAddress((void**)&dUsp, g_Usp);
  cudaGetSymbolAddress((void**)&dWmp, g_Wmp);
  cudaGetSymbolAddress((void**)&dWsp, g_Wsp);

  init_kernel<<<1,512>>>(em, Wm, Um, bm);
  shuf_kernel<<<64,256>>>(dUmp, Um);
  shuf_kernel<<<64,256>>>(dUsp, Us);
  shuf_kernel<<<64,256>>>(dWmp, Wm);
  shuf_kernel<<<64,256>>>(dWsp, Ws);
  layer0_kernel<<<NBLK,NTHR,SMEMB>>>(emb, names, btab, bm, bs);
  for(int l=1;l<LLn;l++)
    layer_kernel<<<NBLK,NTHR,SMEMB>>>(l, emb,
        prop + (size_t)l*Mn*Pp, sup + (size_t)l*Mn*Ssn, bm, bs);
}

// round 8
// speedup vs baseline: 1.2122x; 1.2122x over previous
#include <cuda_runtime.h>
#include <cstddef>

#define Mn   2048
#define LLn  64
#define Pp   4
#define Ssn  2
#define RPB  16
#define NTHR 256
#define NBLK (Mn/RPB)

// smem floats: wbuf 3*16384 (3 x 64KB tiles) | hA 2048 | ids 96
#define OFF_HA (3*16384)
#define OFF_ID (OFF_HA + 2048)
#define SMEMB  ((OFF_ID + 96) * 4)   /* 205184 B */

__device__ float g_EWm[(size_t)LLn * Mn * 512];
__device__ float g_EWs[(size_t)LLn * Mn * 512];
__device__ float g_c0[128];
__device__ float g_z1b[512];
// k-pair packed: [kp(64)][col(512)] float2 = {W[2kp][col], W[2kp+1][col]}
__device__ float g_Ump[65536];
__device__ float g_Usp[65536];
__device__ float g_Wmp[65536];
__device__ float g_Wsp[65536];

typedef unsigned long long u64t;

__device__ __forceinline__ float2 u2f(u64t u){ float2 v; asm("mov.b64 {%0,%1},%2;":"=f"(v.x),"=f"(v.y):"l"(u)); return v; }
__device__ __forceinline__ void fma2(u64t&a, u64t x, u64t w){ asm("fma.rn.f32x2 %0,%1,%2,%0;":"+l"(a):"l"(x),"l"(w)); }
__device__ __forceinline__ float redu(u64t a){ float2 v=u2f(a); return v.x+v.y; }

__device__ __forceinline__ void cpa16(float* sdst, const float* gsrc){
  unsigned s=(unsigned)__cvta_generic_to_shared(sdst);
  asm volatile("cp.async.cg.shared.global [%0],[%1],16;"::"r"(s),"l"(gsrc));
}
__device__ __forceinline__ void cpcommit(){ asm volatile("cp.async.commit_group;":::"memory"); }
__device__ __forceinline__ void cpwait1(){ asm volatile("cp.async.wait_group 1;":::"memory"); }
__device__ __forceinline__ void cpwait0(){ asm volatile("cp.async.wait_group 0;":::"memory"); }

__device__ __forceinline__ float sigf(float x){ return 1.f/(1.f+__expf(-x)); }
__device__ __forceinline__ float tfast(float x){
  x = fminf(fmaxf(x,-15.f),15.f);
  float t = __expf(2.f*x);
  return (t-1.f)/(t+1.f);
}

// Thread layout: 8 warps = 4 teams x 2 warps; team owns rows tr0=4*team..+3.
// Warp wsub covers hidden dims [64*wsub,+64); lane cg owns dims d0=64*wsub+2cg, d0+1.
// Thread's 8 z-columns: gate g -> cols 128*g+co0, +1  (co0 == d0).
// acc[r][c]: u64 {k-even sum, k-odd sum}; c = 2*g + (0|1) selects the column.
__device__ __forceinline__ void gemm(u64t acc[4][8], const float* __restrict__ Wp,
    const float* xs, float* wbuf, int tid, int co0, int tr0)
{
  #pragma unroll
  for(int i=0;i<16;i++) cpa16(wbuf + 4*(tid+256*i), Wp + 4*(tid+256*i));
  cpcommit();
  #pragma unroll
  for(int i=0;i<16;i++) cpa16(wbuf + 16384 + 4*(tid+256*i), Wp + 16384 + 4*(tid+256*i));
  cpcommit();
  #pragma unroll 1
  for(int kt=0;kt<4;kt++){
    if(kt<3) cpwait1(); else cpwait0();
    __syncthreads();
    if(kt<2){
      float* dst = wbuf + ((kt+2)%3)*16384;
      const float* src = Wp + (kt+2)*16384;
      #pragma unroll
      for(int i=0;i<16;i++) cpa16(dst + 4*(tid+256*i), src + 4*(tid+256*i));
      cpcommit();
    }
    const float* wb = wbuf + (kt%3)*16384;
    const float* xb = xs + kt*32;
    #pragma unroll
    for(int kq=0;kq<8;kq++){
      // two k-pairs: kp = 2kq (A), 2kq+1 (B); thread's 8 cols as 4 LDS.128 each
      const ulonglong2* wrA = (const ulonglong2*)(wb + ((2*kq  )*512 + co0)*2);
      const ulonglong2* wrB = (const ulonglong2*)(wb + ((2*kq+1)*512 + co0)*2);
      ulonglong2 a0=wrA[0], a1=wrA[64], a2=wrA[128], a3=wrA[192];
      ulonglong2 b0=wrB[0], b1=wrB[64], b2=wrB[128], b3=wrB[192];
      #pragma unroll
      for(int r=0;r<4;r++){
        ulonglong2 xv = *(const ulonglong2*)(xb + (tr0+r)*128 + kq*4); // {h[4kq..+1]},{h[4kq+2..+3]}
        fma2(acc[r][0], xv.x, a0.x); fma2(acc[r][1], xv.x, a0.y);
        fma2(acc[r][2], xv.x, a1.x); fma2(acc[r][3], xv.x, a1.y);
        fma2(acc[r][4], xv.x, a2.x); fma2(acc[r][5], xv.x, a2.y);
        fma2(acc[r][6], xv.x, a3.x); fma2(acc[r][7], xv.x, a3.y);
        fma2(acc[r][0], xv.y, b0.x); fma2(acc[r][1], xv.y, b0.y);
        fma2(acc[r][2], xv.y, b1.x); fma2(acc[r][3], xv.y, b1.y);
        fma2(acc[r][4], xv.y, b2.x); fma2(acc[r][5], xv.y, b2.y);
        fma2(acc[r][6], xv.y, b3.x); fma2(acc[r][7], xv.y, b3.y);
      }
    }
  }
  __syncthreads();  // protect wbuf reuse by the next gemm
}

__device__ __forceinline__ void zero_acc(u64t acc[4][8]){
  #pragma unroll
  for(int r=0;r<4;r++)
    #pragma unroll
    for(int c=0;c<8;c++) acc[r][c]=0ull;
}

__device__ __forceinline__ void make_z(float2 z[4], const u64t a[8]){
  #pragma unroll
  for(int g=0;g<4;g++) z[g]=make_float2(redu(a[2*g]), redu(a[2*g+1]));
}

// z: i,f,g,o for this thread's dim pair; updates c, returns h.
__device__ __forceinline__ float2 cell1(const float2 z[4], float2& c){
  c.x = sigf(z[1].x)*c.x + sigf(z[0].x)*tfast(z[2].x);
  c.y = sigf(z[1].y)*c.y + sigf(z[0].y)*tfast(z[2].y);
  float2 h;
  h.x = sigf(z[3].x)*tfast(c.x);
  h.y = sigf(z[3].y)*tfast(c.y);
  return h;
}

__global__ void __launch_bounds__(NTHR,1) layer_kernel(int l, float* __restrict__ emb,
  const int* __restrict__ prop, const int* __restrict__ sup,
  const float* __restrict__ bm, const float* __restrict__ bs)
{
  extern __shared__ float smx[];
  float* wbuf = smx;
  float* hA   = smx + OFF_HA;
  int*   ids  = (int*)(smx + OFF_ID);
  const int tid=threadIdx.x, cg=tid&31, wid=tid>>5;
  const int team=wid>>1, wsub=wid&1;
  const int co0 = 64*wsub + 2*cg;
  const int tr0 = 4*team;
  const int lrow0 = blockIdx.x*RPB;
  const int base  = l*Mn + lrow0;

  if(tid<RPB*Pp) ids[tid] = prop[lrow0*Pp + tid];
  else if(tid<RPB*Pp+RPB*Ssn) ids[tid] = sup[lrow0*Ssn + (tid-RPB*Pp)];
  __syncthreads();

  u64t acc[4][8];
  float2 zl[4][4];
  float2 cst[4], z[4];

  // ---- member t=1: z = E_Wm[pid0] + z1b ; c_prev = c0
  {
    float2 c0v = *(const float2*)(g_c0 + co0);
    #pragma unroll
    for(int r=0;r<4;r++){
      const float* e = g_EWm + (size_t)ids[(tr0+r)*Pp]*512;
      #pragma unroll
      for(int g=0;g<4;g++){
        float2 ev = *(const float2*)(e + co0 + 128*g);
        float2 zb = *(const float2*)(g_z1b + co0 + 128*g);
        z[g] = make_float2(ev.x+zb.x, ev.y+zb.y);
      }
      cst[r]=c0v;
      *(float2*)(hA + (tr0+r)*128 + co0) = cell1(z, cst[r]);
    }
  }
  __syncthreads();

  // ---- member t=2..4: z = E_Wm[pid_{t-1}] + h @ Um
  #pragma unroll 1
  for(int t=2;t<=4;t++){
    zero_acc(acc);
    gemm(acc, g_Ump, hA, wbuf, tid, co0, tr0);
    #pragma unroll
    for(int r=0;r<4;r++){
      const float* e = g_EWm + (size_t)ids[(tr0+r)*Pp + (t-1)]*512;
      make_z(z, acc[r]);
      #pragma unroll
      for(int g=0;g<4;g++){
        float2 ev = *(const float2*)(e + co0 + 128*g);
        z[g].x += ev.x; z[g].y += ev.y;
      }
      *(float2*)(hA + (tr0+r)*128 + co0) = cell1(z, cst[r]);
    }
    __syncthreads();
  }
  // hA == h_m

  // ---- zl = b_s + h_m @ Ws  (x-contribution of super step t=2, kept in regs)
  zero_acc(acc);
  gemm(acc, g_Wsp, hA, wbuf, tid, co0, tr0);
  #pragma unroll
  for(int r=0;r<4;r++){
    make_z(zl[r], acc[r]);
    #pragma unroll
    for(int g=0;g<4;g++){
      float2 bv = *(const float2*)(bs + co0 + 128*g);
      zl[r][g].x += bv.x; zl[r][g].y += bv.y;
    }
  }

  // ---- super t=0: z = E_Ws[sid0], zero state
  #pragma unroll
  for(int r=0;r<4;r++){
    const float* e = g_EWs + (size_t)ids[RPB*Pp + (tr0+r)*Ssn]*512;
    #pragma unroll
    for(int g=0;g<4;g++) z[g] = *(const float2*)(e + co0 + 128*g);
    cst[r]=make_float2(0.f,0.f);
    *(float2*)(hA + (tr0+r)*128 + co0) = cell1(z, cst[r]);
  }
  __syncthreads();

  // ---- super t=1: z = E_Ws[sid1] + h @ Us
  zero_acc(acc);
  gemm(acc, g_Usp, hA, wbuf, tid, co0, tr0);
  #pragma unroll
  for(int r=0;r<4;r++){
    const float* e = g_EWs + (size_t)ids[RPB*Pp + (tr0+r)*Ssn + 1]*512;
    make_z(z, acc[r]);
    #pragma unroll
    for(int g=0;g<4;g++){
      float2 ev = *(const float2*)(e + co0 + 128*g);
      z[g].x += ev.x; z[g].y += ev.y;
    }
    *(float2*)(hA + (tr0+r)*128 + co0) = cell1(z, cst[r]);
  }
  __syncthreads();

  // ---- super t=2: z = zl + h @ Us -> h_s
  zero_acc(acc);
  gemm(acc, g_Usp, hA, wbuf, tid, co0, tr0);
  #pragma unroll
  for(int r=0;r<4;r++){
    make_z(z, acc[r]);
    #pragma unroll
    for(int g=0;g<4;g++){ z[g].x += zl[r][g].x; z[g].y += zl[r][g].y; }
    *(float2*)(hA + (tr0+r)*128 + co0) = cell1(z, cst[r]);
  }
  __syncthreads();

  // ---- write emb rows
  {
    float4* dst=(float4*)(emb + (size_t)base*128);
    const float4* src=(const float4*)hA;
    dst[tid]     = src[tid];
    dst[tid+256] = src[tid+256];
  }

  // ---- produce z-tables for this layer's rows
  zero_acc(acc);
  gemm(acc, g_Wmp, hA, wbuf, tid, co0, tr0);
  #pragma unroll
  for(int r=0;r<4;r++){
    float* dr = g_EWm + (size_t)(base+tr0+r)*512;
    make_z(z, acc[r]);
    #pragma unroll
    for(int g=0;g<4;g++){
      float2 bv = *(const float2*)(bm + co0 + 128*g);
      *(float2*)(dr + co0 + 128*g) = make_float2(z[g].x+bv.x, z[g].y+bv.y);
    }
  }
  zero_acc(acc);
  gemm(acc, g_Wsp, hA, wbuf, tid, co0, tr0);
  #pragma unroll
  for(int r=0;r<4;r++){
    float* dr = g_EWs + (size_t)(base+tr0+r)*512;
    make_z(z, acc[r]);
    #pragma unroll
    for(int g=0;g<4;g++){
      float2 bv = *(const float2*)(bs + co0 + 128*g);
      *(float2*)(dr + co0 + 128*g) = make_float2(z[g].x+bv.x, z[g].y+bv.y);
    }
  }
}

__global__ void __launch_bounds__(NTHR,1) layer0_kernel(float* __restrict__ emb,
  const int* __restrict__ names, const float* __restrict__ btab,
  const float* __restrict__ bm, const float* __restrict__ bs)
{
  extern __shared__ float smx[];
  float* wbuf=smx; float* hA=smx+OFF_HA;
  const int tid=threadIdx.x, cg=tid&31, wid=tid>>5;
  const int team=wid>>1, wsub=wid&1;
  const int co0 = 64*wsub + 2*cg;
  const int tr0 = 4*team;
  const int row0 = blockIdx.x*RPB;

  for(int i=tid;i<RPB*128;i+=NTHR){
    int r=i>>7, k=i&127;
    float v = btab[names[row0+r]*128 + k];
    hA[i]=v;
    emb[(size_t)(row0+r)*128 + k]=v;
  }
  __syncthreads();

  u64t acc[4][8];
  float2 z[4];
  zero_acc(acc);
  gemm(acc, g_Wmp, hA, wbuf, tid, co0, tr0);
  #pragma unroll
  for(int r=0;r<4;r++){
    float* dr = g_EWm + (size_t)(row0+tr0+r)*512;
    make_z(z, acc[r]);
    #pragma unroll
    for(int g=0;g<4;g++){
      float2 bv = *(const float2*)(bm + co0 + 128*g);
      *(float2*)(dr + co0 + 128*g) = make_float2(z[g].x+bv.x, z[g].y+bv.y);
    }
  }
  zero_acc(acc);
  gemm(acc, g_Wsp, hA, wbuf, tid, co0, tr0);
  #pragma unroll
  for(int r=0;r<4;r++){
    float* dr = g_EWs + (size_t)(row0+tr0+r)*512;
    make_z(z, acc[r]);
    #pragma unroll
    for(int g=0;g<4;g++){
      float2 bv = *(const float2*)(bs + co0 + 128*g);
      *(float2*)(dr + co0 + 128*g) = make_float2(z[g].x+bv.x, z[g].y+bv.y);
    }
  }
}

// fused pre-shuffle: 4 matrices -> k-pair-packed float2 tables.
// 32768 float2 entries per matrix -> 128 blocks x 256 threads per matrix.
__global__ void shuf_kernel(const float* __restrict__ Um, const float* __restrict__ Us,
                            const float* __restrict__ Wm, const float* __restrict__ Ws)
{
  int b=blockIdx.x, seg=b>>7;
  const float* src = (seg==0)?Um:(seg==1)?Us:(seg==2)?Wm:Ws;
  float* dst = (seg==0)?g_Ump:(seg==1)?g_Usp:(seg==2)?g_Wmp:g_Wsp;
  int i=(b&127)*256+threadIdx.x;         // 0..32767
  int kp=i>>9, col=i&511;                // kp 0..63, col 0..511
  ((float2*)dst)[i] = make_float2(src[(2*kp)*512+col], src[(2*kp+1)*512+col]);
}

// One-shot constants: z0 = em@Wm + bm -> c0, h0 -> z1b = h0@Um
__global__ void init_kernel(const float* __restrict__ em, const float* __restrict__ Wm,
                            const float* __restrict__ Um, const float* __restrict__ bm)
{
  __shared__ float z0[512]; __shared__ float h0[128]; __shared__ float ems[128];
  int t=threadIdx.x;
  if(t<128) ems[t]=em[t];
  __syncthreads();
  float s=bm[t];
  for(int k=0;k<128;k++) s += ems[k]*Wm[k*512+t];
  z0[t]=s;
  __syncthreads();
  if(t<128){
    float zi=z0[t], zg=z0[256+t], zo=z0[384+t];
    float c = (1.f/(1.f+expf(-zi)))*tanhf(zg);
    g_c0[t]=c;
    h0[t]=(1.f/(1.f+expf(-zo)))*tanhf(c);
  }
  __syncthreads();
  float s2=0.f;
  for(int k=0;k<128;k++) s2 += h0[k]*Um[k*512+t];
  g_z1b[t]=s2;
}

extern "C" void kernel_launch(void* const* d_in, const int* in_sizes, int n_in,
                              void* d_out, int out_size)
{
  const int*   names=(const int*)d_in[0];
  const int*   prop =(const int*)d_in[1];
  const int*   sup  =(const int*)d_in[2];
  const float* btab =(const float*)d_in[3];
  const float* Wm   =(const float*)d_in[4];
  const float* Um   =(const float*)d_in[5];
  const float* bm   =(const float*)d_in[6];
  const float* Ws   =(const float*)d_in[7];
  const float* Us   =(const float*)d_in[8];
  const float* bs   =(const float*)d_in[9];
  const float* em   =(const float*)d_in[10];
  float* emb=(float*)d_out;

  cudaFuncSetAttribute(layer_kernel,  cudaFuncAttributeMaxDynamicSharedMemorySize, SMEMB);
  cudaFuncSetAttribute(layer0_kernel, cudaFuncAttributeMaxDynamicSharedMemorySize, SMEMB);

  init_kernel<<<1,512>>>(em, Wm, Um, bm);
  shuf_kernel<<<512,256>>>(Um, Us, Wm, Ws);
  layer0_kernel<<<NBLK,NTHR,SMEMB>>>(emb, names, btab, bm, bs);
  for(int l=1;l<LLn;l++)
    layer_kernel<<<NBLK,NTHR,SMEMB>>>(l, emb,
        prop + (size_t)l*Mn*Pp, sup + (size_t)l*Mn*Ssn, bm, bs);
}

// round 9
// speedup vs baseline: 1.2279x; 1.0129x over previous
#include <cuda_runtime.h>
#include <cstddef>

#define Mn   2048
#define LLn  64
#define Pp   4
#define Ssn  2
#define RPB  16
#define NTHR 512
#define NBLK (Mn/RPB)

// smem floats: wbuf 3*16384 (3 x 64KB tiles) | hA 2048 | ids 96
#define OFF_HA (3*16384)
#define OFF_ID (OFF_HA + 2048)
#define SMEMB  ((OFF_ID + 96) * 4)   /* 205184 B */

__device__ float g_EWm[(size_t)LLn * Mn * 512];
__device__ float g_EWs[(size_t)LLn * Mn * 512];
__device__ float g_c0[128];
__device__ float g_z1b[512];
// k-pair packed: [kp(64)][col(512)] float2 = {W[2kp][col], W[2kp+1][col]}
__device__ float g_Ump[65536];
__device__ float g_Usp[65536];
__device__ float g_Wmp[65536];
__device__ float g_Wsp[65536];

typedef unsigned long long u64t;

__device__ __forceinline__ float2 u2f(u64t u){ float2 v; asm("mov.b64 {%0,%1},%2;":"=f"(v.x),"=f"(v.y):"l"(u)); return v; }
__device__ __forceinline__ void fma2(u64t&a, u64t x, u64t w){ asm("fma.rn.f32x2 %0,%1,%2,%0;":"+l"(a):"l"(x),"l"(w)); }
__device__ __forceinline__ float redu(u64t a){ float2 v=u2f(a); return v.x+v.y; }

__device__ __forceinline__ void cpa16(float* sdst, const float* gsrc){
  unsigned s=(unsigned)__cvta_generic_to_shared(sdst);
  asm volatile("cp.async.cg.shared.global [%0],[%1],16;"::"r"(s),"l"(gsrc));
}
__device__ __forceinline__ void cpcommit(){ asm volatile("cp.async.commit_group;":::"memory"); }
__device__ __forceinline__ void cpwait1(){ asm volatile("cp.async.wait_group 1;":::"memory"); }
__device__ __forceinline__ void cpwait0(){ asm volatile("cp.async.wait_group 0;":::"memory"); }

__device__ __forceinline__ float sigf(float x){ return 1.f/(1.f+__expf(-x)); }
__device__ __forceinline__ float tfast(float x){
  x = fminf(fmaxf(x,-15.f),15.f);
  float t = __expf(2.f*x);
  return (t-1.f)/(t+1.f);
}

// Thread layout: 16 warps = 4 teams x 4 warps; team=wid>>2 owns rows tr0=4*team..+3.
// Warp wsub=wid&3 covers hidden dims [32*wsub, +32); lane cg owns dim d0=32*wsub+cg.
// Thread's 4 z-columns: gate g -> col 128*g + d0.
// acc[r][g]: u64 {k-even sum, k-odd sum} for that column, row tr0+r.
__device__ __forceinline__ void gemm(u64t acc[4][4], const float* __restrict__ Wp,
    const float* xs, float* wbuf, int tid, int d0, int tr0)
{
  #pragma unroll
  for(int i=0;i<8;i++) cpa16(wbuf + 4*(tid+512*i), Wp + 4*(tid+512*i));
  cpcommit();
  #pragma unroll
  for(int i=0;i<8;i++) cpa16(wbuf + 16384 + 4*(tid+512*i), Wp + 16384 + 4*(tid+512*i));
  cpcommit();
  #pragma unroll 1
  for(int kt=0;kt<4;kt++){
    if(kt<3) cpwait1(); else cpwait0();
    __syncthreads();
    if(kt<2){
      float* dst = wbuf + ((kt+2)%3)*16384;
      const float* src = Wp + (kt+2)*16384;
      #pragma unroll
      for(int i=0;i<8;i++) cpa16(dst + 4*(tid+512*i), src + 4*(tid+512*i));
      cpcommit();
    }
    const float* wb = wbuf + (kt%3)*16384;      // [kp(16)][col(512)] float2
    const float* xb = xs + kt*32;
    #pragma unroll
    for(int kq=0;kq<8;kq++){
      // kp = 2kq (A) and 2kq+1 (B); per gate one LDS.64 each
      const u64t* wA = (const u64t*)wb + (2*kq  )*512 + d0;
      const u64t* wB = (const u64t*)wb + (2*kq+1)*512 + d0;
      u64t a0=wA[0], a1=wA[128], a2=wA[256], a3=wA[384];
      u64t b0=wB[0], b1=wB[128], b2=wB[256], b3=wB[384];
      #pragma unroll
      for(int r=0;r<4;r++){
        ulonglong2 xv = *(const ulonglong2*)(xb + (tr0+r)*128 + kq*4); // {x[4kq..+1]},{x[4kq+2..+3]}
        fma2(acc[r][0], xv.x, a0); fma2(acc[r][1], xv.x, a1);
        fma2(acc[r][2], xv.x, a2); fma2(acc[r][3], xv.x, a3);
        fma2(acc[r][0], xv.y, b0); fma2(acc[r][1], xv.y, b1);
        fma2(acc[r][2], xv.y, b2); fma2(acc[r][3], xv.y, b3);
      }
    }
  }
  __syncthreads();  // protect wbuf reuse by the next gemm
}

__device__ __forceinline__ void zero_acc(u64t acc[4][4]){
  #pragma unroll
  for(int r=0;r<4;r++)
    #pragma unroll
    for(int g=0;g<4;g++) acc[r][g]=0ull;
}

// z: i,f,g,o scalars for this thread's dim; updates c, returns h.
__device__ __forceinline__ float cell1(const float z[4], float& c){
  c = sigf(z[1])*c + sigf(z[0])*tfast(z[2]);
  return sigf(z[3])*tfast(c);
}

__global__ void __launch_bounds__(NTHR,1) layer_kernel(int l, float* __restrict__ emb,
  const int* __restrict__ prop, const int* __restrict__ sup,
  const float* __restrict__ bm, const float* __restrict__ bs)
{
  extern __shared__ float smx[];
  float* wbuf = smx;
  float* hA   = smx + OFF_HA;
  int*   ids  = (int*)(smx + OFF_ID);
  const int tid=threadIdx.x, cg=tid&31, wid=tid>>5;
  const int team=wid>>2, wsub=wid&3;
  const int d0  = 32*wsub + cg;
  const int tr0 = 4*team;
  const int lrow0 = blockIdx.x*RPB;
  const int base  = l*Mn + lrow0;

  if(tid<RPB*Pp) ids[tid] = prop[lrow0*Pp + tid];
  else if(tid<RPB*Pp+RPB*Ssn) ids[tid] = sup[lrow0*Ssn + (tid-RPB*Pp)];
  __syncthreads();

  u64t acc[4][4];
  float zl[4][4];
  float cst[4], z[4];

  // ---- member t=1: z = E_Wm[pid0] + z1b ; c_prev = c0
  {
    float c0v = g_c0[d0];
    #pragma unroll
    for(int r=0;r<4;r++){
      const float* e = g_EWm + (size_t)ids[(tr0+r)*Pp]*512;
      #pragma unroll
      for(int g=0;g<4;g++) z[g] = e[128*g+d0] + g_z1b[128*g+d0];
      cst[r]=c0v;
      hA[(tr0+r)*128 + d0] = cell1(z, cst[r]);
    }
  }
  __syncthreads();

  // ---- member t=2..4: z = E_Wm[pid_{t-1}] + h @ Um
  #pragma unroll 1
  for(int t=2;t<=4;t++){
    zero_acc(acc);
    gemm(acc, g_Ump, hA, wbuf, tid, d0, tr0);
    #pragma unroll
    for(int r=0;r<4;r++){
      const float* e = g_EWm + (size_t)ids[(tr0+r)*Pp + (t-1)]*512;
      #pragma unroll
      for(int g=0;g<4;g++) z[g] = redu(acc[r][g]) + e[128*g+d0];
      hA[(tr0+r)*128 + d0] = cell1(z, cst[r]);
    }
    __syncthreads();
  }
  // hA == h_m

  // ---- zl = b_s + h_m @ Ws  (x-contribution of super step t=2, kept in regs)
  zero_acc(acc);
  gemm(acc, g_Wsp, hA, wbuf, tid, d0, tr0);
  #pragma unroll
  for(int r=0;r<4;r++)
    #pragma unroll
    for(int g=0;g<4;g++) zl[r][g] = redu(acc[r][g]) + bs[128*g+d0];

  // ---- super t=0: z = E_Ws[sid0], zero state
  #pragma unroll
  for(int r=0;r<4;r++){
    const float* e = g_EWs + (size_t)ids[RPB*Pp + (tr0+r)*Ssn]*512;
    #pragma unroll
    for(int g=0;g<4;g++) z[g] = e[128*g+d0];
    cst[r]=0.f;
    hA[(tr0+r)*128 + d0] = cell1(z, cst[r]);
  }
  __syncthreads();

  // ---- super t=1: z = E_Ws[sid1] + h @ Us
  zero_acc(acc);
  gemm(acc, g_Usp, hA, wbuf, tid, d0, tr0);
  #pragma unroll
  for(int r=0;r<4;r++){
    const float* e = g_EWs + (size_t)ids[RPB*Pp + (tr0+r)*Ssn + 1]*512;
    #pragma unroll
    for(int g=0;g<4;g++) z[g] = redu(acc[r][g]) + e[128*g+d0];
    hA[(tr0+r)*128 + d0] = cell1(z, cst[r]);
  }
  __syncthreads();

  // ---- super t=2: z = zl + h @ Us -> h_s
  zero_acc(acc);
  gemm(acc, g_Usp, hA, wbuf, tid, d0, tr0);
  #pragma unroll
  for(int r=0;r<4;r++){
    #pragma unroll
    for(int g=0;g<4;g++) z[g] = redu(acc[r][g]) + zl[r][g];
    hA[(tr0+r)*128 + d0] = cell1(z, cst[r]);
  }
  __syncthreads();

  // ---- write emb rows (coalesced from smem)
  ((float4*)(emb + (size_t)base*128))[tid] = ((const float4*)hA)[tid];

  // ---- produce z-tables for this layer's rows
  zero_acc(acc);
  gemm(acc, g_Wmp, hA, wbuf, tid, d0, tr0);
  #pragma unroll
  for(int r=0;r<4;r++){
    float* dr = g_EWm + (size_t)(base+tr0+r)*512;
    #pragma unroll
    for(int g=0;g<4;g++) dr[128*g+d0] = redu(acc[r][g]) + bm[128*g+d0];
  }
  zero_acc(acc);
  gemm(acc, g_Wsp, hA, wbuf, tid, d0, tr0);
  #pragma unroll
  for(int r=0;r<4;r++){
    float* dr = g_EWs + (size_t)(base+tr0+r)*512;
    #pragma unroll
    for(int g=0;g<4;g++) dr[128*g+d0] = redu(acc[r][g]) + bs[128*g+d0];
  }
}

__global__ void __launch_bounds__(NTHR,1) layer0_kernel(float* __restrict__ emb,
  const int* __restrict__ names, const float* __restrict__ btab,
  const float* __restrict__ bm, const float* __restrict__ bs)
{
  extern __shared__ float smx[];
  float* wbuf=smx; float* hA=smx+OFF_HA;
  const int tid=threadIdx.x, cg=tid&31, wid=tid>>5;
  const int team=wid>>2, wsub=wid&3;
  const int d0  = 32*wsub + cg;
  const int tr0 = 4*team;
  const int row0 = blockIdx.x*RPB;

  for(int i=tid;i<RPB*128;i+=NTHR){
    int r=i>>7, k=i&127;
    float v = btab[names[row0+r]*128 + k];
    hA[i]=v;
    emb[(size_t)(row0+r)*128 + k]=v;
  }
  __syncthreads();

  u64t acc[4][4];
  zero_acc(acc);
  gemm(acc, g_Wmp, hA, wbuf, tid, d0, tr0);
  #pragma unroll
  for(int r=0;r<4;r++){
    float* dr = g_EWm + (size_t)(row0+tr0+r)*512;
    #pragma unroll
    for(int g=0;g<4;g++) dr[128*g+d0] = redu(acc[r][g]) + bm[128*g+d0];
  }
  zero_acc(acc);
  gemm(acc, g_Wsp, hA, wbuf, tid, d0, tr0);
  #pragma unroll
  for(int r=0;r<4;r++){
    float* dr = g_EWs + (size_t)(row0+tr0+r)*512;
    #pragma unroll
    for(int g=0;g<4;g++) dr[128*g+d0] = redu(acc[r][g]) + bs[128*g+d0];
  }
}

// fused pre-shuffle: 4 matrices -> k-pair-packed float2 tables.
// 32768 float2 entries per matrix -> 128 blocks x 256 threads per matrix.
__global__ void shuf_kernel(const float* __restrict__ Um, const float* __restrict__ Us,
                            const float* __restrict__ Wm, const float* __restrict__ Ws)
{
  int b=blockIdx.x, seg=b>>7;
  const float* src = (seg==0)?Um:(seg==1)?Us:(seg==2)?Wm:Ws;
  float* dst = (seg==0)?g_Ump:(seg==1)?g_Usp:(seg==2)?g_Wmp:g_Wsp;
  int i=(b&127)*256+threadIdx.x;         // 0..32767
  int kp=i>>9, col=i&511;                // kp 0..63, col 0..511
  ((float2*)dst)[i] = make_float2(src[(2*kp)*512+col], src[(2*kp+1)*512+col]);
}

// One-shot constants: z0 = em@Wm + bm -> c0, h0 -> z1b = h0@Um
__global__ void init_kernel(const float* __restrict__ em, const float* __restrict__ Wm,
                            const float* __restrict__ Um, const float* __restrict__ bm)
{
  __shared__ float z0[512]; __shared__ float h0[128]; __shared__ float ems[128];
  int t=threadIdx.x;
  if(t<128) ems[t]=em[t];
  __syncthreads();
  float s=bm[t];
  for(int k=0;k<128;k++) s += ems[k]*Wm[k*512+t];
  z0[t]=s;
  __syncthreads();
  if(t<128){
    float zi=z0[t], zg=z0[256+t], zo=z0[384+t];
    float c = (1.f/(1.f+expf(-zi)))*tanhf(zg);
    g_c0[t]=c;
    h0[t]=(1.f/(1.f+expf(-zo)))*tanhf(c);
  }
  __syncthreads();
  float s2=0.f;
  for(int k=0;k<128;k++) s2 += h0[k]*Um[k*512+t];
  g_z1b[t]=s2;
}

extern "C" void kernel_launch(void* const* d_in, const int* in_sizes, int n_in,
                              void* d_out, int out_size)
{
  const int*   names=(const int*)d_in[0];
  const int*   prop =(const int*)d_in[1];
  const int*   sup  =(const int*)d_in[2];
  const float* btab =(const float*)d_in[3];
  const float* Wm   =(const float*)d_in[4];
  const float* Um   =(const float*)d_in[5];
  const float* bm   =(const float*)d_in[6];
  const float* Ws   =(const float*)d_in[7];
  const float* Us   =(const float*)d_in[8];
  const float* bs   =(const float*)d_in[9];
  const float* em   =(const float*)d_in[10];
  float* emb=(float*)d_out;

  cudaFuncSetAttribute(layer_kernel,  cudaFuncAttributeMaxDynamicSharedMemorySize, SMEMB);
  cudaFuncSetAttribute(layer0_kernel, cudaFuncAttributeMaxDynamicSharedMemorySize, SMEMB);

  init_kernel<<<1,512>>>(em, Wm, Um, bm);
  shuf_kernel<<<512,256>>>(Um, Us, Wm, Ws);
  layer0_kernel<<<NBLK,NTHR,SMEMB>>>(emb, names, btab, bm, bs);
  for(int l=1;l<LLn;l++)
    layer_kernel<<<NBLK,NTHR,SMEMB>>>(l, emb,
        prop + (size_t)l*Mn*Pp, sup + (size_t)l*Mn*Ssn, bm, bs);
}

// round 10
// speedup vs baseline: 1.4237x; 1.1595x over previous
#include <cuda_runtime.h>
#include <cstddef>

#define Mn   2048
#define LLn  64
#define Pp   4
#define Ssn  2
#define RPB  16
#define NTHR 544              /* 16 consumer warps + 1 producer warp */
#define NCONS 512
#define NBLK (Mn/RPB)
#define NBUF 6
#define TILE_FLOATS 8192      /* 16 k x 512 cols x f32 = 32KB */
#define TILE_BYTES  32768

// smem floats: ring 6*8192 | hA 2048 | ids 96 | mbarriers (12 x 8B)
#define OFF_HA  49152
#define OFF_ID  51200
#define OFF_BAR 51296
#define SMEMB   (OFF_BAR*4 + 96)   /* 205280 B */

__device__ __align__(256) float g_EWm[(size_t)LLn * Mn * 512];
__device__ __align__(256) float g_EWs[(size_t)LLn * Mn * 512];
__device__ float g_c0[128];
__device__ float g_z1b[512];
// k-pair packed: [kp(64)][col(512)] float2 = {W[2kp][col], W[2kp+1][col]}
__device__ __align__(256) float g_Ump[65536];
__device__ __align__(256) float g_Usp[65536];
__device__ __align__(256) float g_Wmp[65536];
__device__ __align__(256) float g_Wsp[65536];

typedef unsigned long long u64t;

__device__ __forceinline__ float2 u2f(u64t u){ float2 v; asm("mov.b64 {%0,%1},%2;":"=f"(v.x),"=f"(v.y):"l"(u)); return v; }
__device__ __forceinline__ void fma2(u64t&a, u64t x, u64t w){ asm("fma.rn.f32x2 %0,%1,%2,%0;":"+l"(a):"l"(x),"l"(w)); }
__device__ __forceinline__ float redu(u64t a){ float2 v=u2f(a); return v.x+v.y; }

__device__ __forceinline__ unsigned smu32(const void* p){
  unsigned a; asm("{ .reg .u64 t; cvta.to.shared.u64 t, %1; cvt.u32.u64 %0, t; }":"=r"(a):"l"(p)); return a;
}
__device__ __forceinline__ void mb_init(unsigned mb, unsigned cnt){
  asm volatile("mbarrier.init.shared.b64 [%0], %1;"::"r"(mb),"r"(cnt):"memory");
}
__device__ __forceinline__ void mb_wait(unsigned mb, int ph){
  asm volatile("{\n\t.reg .pred P;\n\tWL%=:\n\tmbarrier.try_wait.parity.acquire.cta.shared::cta.b64 P, [%0], %1, 0x989680;\n\t@P bra WD%=;\n\tbra WL%=;\n\tWD%=:\n\t}"
    ::"r"(mb),"r"(ph):"memory");
}
__device__ __forceinline__ void mb_arrive(unsigned mb){
  asm volatile("mbarrier.arrive.shared.b64 _, [%0];"::"r"(mb):"memory");
}
__device__ __forceinline__ void mb_expect_tx(unsigned mb, unsigned bytes){
  asm volatile("mbarrier.arrive.expect_tx.shared.b64 _, [%0], %1;"::"r"(mb),"r"(bytes):"memory");
}
__device__ __forceinline__ void bulk_cp(unsigned dst, const float* src, unsigned bytes, unsigned mb){
  asm volatile("cp.async.bulk.shared::cta.global.mbarrier::complete_tx::bytes [%0], [%1], %2, [%3];"
    ::"r"(dst),"l"(src),"r"(bytes),"r"(mb):"memory");
}
#define CBAR() asm volatile("bar.sync 1, %0;"::"n"(NCONS):"memory")

__device__ __forceinline__ float sigf(float x){ return 1.f/(1.f+__expf(-x)); }
__device__ __forceinline__ float tfast(float x){
  x = fminf(fmaxf(x,-15.f),15.f);
  float t = __expf(2.f*x);
  return (t-1.f)/(t+1.f);
}

// ---------------- producer: stream npass*8 tiles through the 6-ring ----------------
__device__ __forceinline__ void producer(unsigned barb, unsigned smbase,
    const float* const* sched, int npass)
{
  int i=0;
  #pragma unroll 1
  for(int p=0;p<npass;p++){
    const float* W = sched[p];
    #pragma unroll 1
    for(int t=0;t<8;t++,i++){
      int s = i % NBUF;
      unsigned fb = barb + s*16;       // full barrier
      if(i >= NBUF) mb_wait(fb + 8, ((i-NBUF)/NBUF)&1);   // empty barrier
      mb_expect_tx(fb, TILE_BYTES);
      bulk_cp(smbase + s*TILE_BYTES, W + t*TILE_FLOATS, TILE_BYTES, fb);
    }
  }
}

// ---------------- consumer: one 512-col GEMM pass over 8 pipelined tiles -----------
// Thread layout: 16 warps = 4 teams x 4 warps; team=wid>>2 owns rows tr0=4*team..+3.
// Warp wsub=wid&3 covers dims [32*wsub,+32); lane cg owns dim d0=32*wsub+cg.
// Thread's 4 z-cols: gate g -> col 128*g+d0. acc[r][g]: u64 {k-even, k-odd} sums.
__device__ __forceinline__ void gemm_pipe(u64t acc[4][4], const float* xs,
    const float* bufbase, unsigned barb, int d0, int tr0, int cg, int& tc)
{
  #pragma unroll 1
  for(int t=0;t<8;t++){
    int s = tc % NBUF;
    unsigned fb = barb + s*16;
    mb_wait(fb, (tc/NBUF)&1);
    const u64t* wb = (const u64t*)(bufbase + s*TILE_FLOATS);
    const float* xb = xs + 16*t;
    #pragma unroll
    for(int kq=0;kq<4;kq++){
      const u64t* wA = wb + (2*kq  )*512 + d0;
      const u64t* wB = wb + (2*kq+1)*512 + d0;
      u64t a0=wA[0], a1=wA[128], a2=wA[256], a3=wA[384];
      u64t b0=wB[0], b1=wB[128], b2=wB[256], b3=wB[384];
      #pragma unroll
      for(int r=0;r<4;r++){
        ulonglong2 xv = *(const ulonglong2*)(xb + (tr0+r)*128 + 4*kq);
        fma2(acc[r][0], xv.x, a0); fma2(acc[r][1], xv.x, a1);
        fma2(acc[r][2], xv.x, a2); fma2(acc[r][3], xv.x, a3);
        fma2(acc[r][0], xv.y, b0); fma2(acc[r][1], xv.y, b1);
        fma2(acc[r][2], xv.y, b2); fma2(acc[r][3], xv.y, b3);
      }
    }
    __syncwarp();
    if(cg==0) mb_arrive(fb + 8);
    tc++;
  }
}

__device__ __forceinline__ void zero_acc(u64t acc[4][4]){
  #pragma unroll
  for(int r=0;r<4;r++)
    #pragma unroll
    for(int g=0;g<4;g++) acc[r][g]=0ull;
}

// z: i,f,g,o scalars for this thread's dim; updates c, returns h.
__device__ __forceinline__ float cell1(const float z[4], float& c){
  c = sigf(z[1])*c + sigf(z[0])*tfast(z[2]);
  return sigf(z[3])*tfast(c);
}

__global__ void __launch_bounds__(NTHR,1) layer_kernel(int l, float* __restrict__ emb,
  const int* __restrict__ prop, const int* __restrict__ sup,
  const float* __restrict__ bm, const float* __restrict__ bs)
{
  extern __shared__ float smx[];
  float* hA  = smx + OFF_HA;
  int*  ids  = (int*)(smx + OFF_ID);
  const int tid=threadIdx.x, cg=tid&31, wid=tid>>5;
  const unsigned smbase = smu32(smx);
  const unsigned barb   = smbase + OFF_BAR*4;
  const int lrow0 = blockIdx.x*RPB;
  const int base  = l*Mn + lrow0;

  if(tid==0){
    #pragma unroll
    for(int s=0;s<NBUF;s++){ mb_init(barb+s*16, 1); mb_init(barb+s*16+8, 16); }
  }
  if(tid<RPB*Pp) ids[tid] = prop[lrow0*Pp + tid];
  else if(tid<RPB*Pp+RPB*Ssn) ids[tid] = sup[lrow0*Ssn + (tid-RPB*Pp)];
  __syncthreads();

  if(wid==16){
    if(cg==0){
      const float* sched[8]={g_Ump,g_Ump,g_Ump,g_Wsp,g_Usp,g_Usp,g_Wmp,g_Wsp};
      producer(barb, smbase, sched, 8);
    }
    return;
  }

  const int team=wid>>2, wsub=wid&3;
  const int d0  = 32*wsub + cg;
  const int tr0 = 4*team;
  int tc = 0;

  u64t acc[4][4];
  float zl[4][4], zz[4][4];
  float cst[4], z[4];

  // ---- member t=1: z = E_Wm[pid0] + z1b ; c_prev = c0
  {
    float c0v = g_c0[d0];
    #pragma unroll
    for(int r=0;r<4;r++){
      const float* e = g_EWm + (size_t)ids[(tr0+r)*Pp]*512;
      #pragma unroll
      for(int g=0;g<4;g++) z[g] = e[128*g+d0] + g_z1b[128*g+d0];
      cst[r]=c0v;
      hA[(tr0+r)*128 + d0] = cell1(z, cst[r]);
    }
  }
  CBAR();

  // ---- member t=2..4: z = E_Wm[pid_{t-1}] + h @ Um
  #pragma unroll 1
  for(int t=2;t<=4;t++){
    zero_acc(acc);
    gemm_pipe(acc, hA, smx, barb, d0, tr0, cg, tc);
    #pragma unroll
    for(int r=0;r<4;r++){
      const float* e = g_EWm + (size_t)ids[(tr0+r)*Pp + (t-1)]*512;
      #pragma unroll
      for(int g=0;g<4;g++) zz[r][g] = redu(acc[r][g]) + e[128*g+d0];
    }
    CBAR();                       // all warps done reading hA
    #pragma unroll
    for(int r=0;r<4;r++) hA[(tr0+r)*128 + d0] = cell1(zz[r], cst[r]);
    CBAR();                       // new h visible
  }
  // hA == h_m

  // ---- zl = b_s + h_m @ Ws  (x-contribution of super t=2, kept in regs)
  zero_acc(acc);
  gemm_pipe(acc, hA, smx, barb, d0, tr0, cg, tc);
  #pragma unroll
  for(int r=0;r<4;r++)
    #pragma unroll
    for(int g=0;g<4;g++) zl[r][g] = redu(acc[r][g]) + bs[128*g+d0];
  CBAR();                         // all warps done reading h_m

  // ---- super t=0: z = E_Ws[sid0], zero state
  #pragma unroll
  for(int r=0;r<4;r++){
    const float* e = g_EWs + (size_t)ids[RPB*Pp + (tr0+r)*Ssn]*512;
    #pragma unroll
    for(int g=0;g<4;g++) z[g] = e[128*g+d0];
    cst[r]=0.f;
    hA[(tr0+r)*128 + d0] = cell1(z, cst[r]);
  }
  CBAR();

  // ---- super t=1: z = E_Ws[sid1] + h @ Us
  zero_acc(acc);
  gemm_pipe(acc, hA, smx, barb, d0, tr0, cg, tc);
  #pragma unroll
  for(int r=0;r<4;r++){
    const float* e = g_EWs + (size_t)ids[RPB*Pp + (tr0+r)*Ssn + 1]*512;
    #pragma unroll
    for(int g=0;g<4;g++) zz[r][g] = redu(acc[r][g]) + e[128*g+d0];
  }
  CBAR();
  #pragma unroll
  for(int r=0;r<4;r++) hA[(tr0+r)*128 + d0] = cell1(zz[r], cst[r]);
  CBAR();

  // ---- super t=2: z = zl + h @ Us -> h_s
  zero_acc(acc);
  gemm_pipe(acc, hA, smx, barb, d0, tr0, cg, tc);
  #pragma unroll
  for(int r=0;r<4;r++)
    #pragma unroll
    for(int g=0;g<4;g++) zz[r][g] = redu(acc[r][g]) + zl[r][g];
  CBAR();
  #pragma unroll
  for(int r=0;r<4;r++) hA[(tr0+r)*128 + d0] = cell1(zz[r], cst[r]);
  CBAR();

  // ---- write emb rows (coalesced from smem)
  ((float4*)(emb + (size_t)base*128))[tid] = ((const float4*)hA)[tid];

  // ---- produce z-tables for this layer's rows (read hA only; no more hA writes)
  zero_acc(acc);
  gemm_pipe(acc, hA, smx, barb, d0, tr0, cg, tc);
  #pragma unroll
  for(int r=0;r<4;r++){
    float* dr = g_EWm + (size_t)(base+tr0+r)*512;
    #pragma unroll
    for(int g=0;g<4;g++) dr[128*g+d0] = redu(acc[r][g]) + bm[128*g+d0];
  }
  zero_acc(acc);
  gemm_pipe(acc, hA, smx, barb, d0, tr0, cg, tc);
  #pragma unroll
  for(int r=0;r<4;r++){
    float* dr = g_EWs + (size_t)(base+tr0+r)*512;
    #pragma unroll
    for(int g=0;g<4;g++) dr[128*g+d0] = redu(acc[r][g]) + bs[128*g+d0];
  }
}

__global__ void __launch_bounds__(NTHR,1) layer0_kernel(float* __restrict__ emb,
  const int* __restrict__ names, const float* __restrict__ btab,
  const float* __restrict__ bm, const float* __restrict__ bs)
{
  extern __shared__ float smx[];
  float* hA = smx + OFF_HA;
  const int tid=threadIdx.x, cg=tid&31, wid=tid>>5;
  const unsigned smbase = smu32(smx);
  const unsigned barb   = smbase + OFF_BAR*4;
  const int row0 = blockIdx.x*RPB;

  if(tid==0){
    #pragma unroll
    for(int s=0;s<NBUF;s++){ mb_init(barb+s*16, 1); mb_init(barb+s*16+8, 16); }
  }
  for(int i=tid;i<RPB*128;i+=NTHR){
    int r=i>>7, k=i&127;
    float v = btab[names[row0+r]*128 + k];
    hA[i]=v;
    emb[(size_t)(row0+r)*128 + k]=v;
  }
  __syncthreads();

  if(wid==16){
    if(cg==0){
      const float* sched[2]={g_Wmp,g_Wsp};
      producer(barb, smbase, sched, 2);
    }
    return;
  }

  const int team=wid>>2, wsub=wid&3;
  const int d0  = 32*wsub + cg;
  const int tr0 = 4*team;
  int tc = 0;

  u64t acc[4][4];
  zero_acc(acc);
  gemm_pipe(acc, hA, smx, barb, d0, tr0, cg, tc);
  #pragma unroll
  for(int r=0;r<4;r++){
    float* dr = g_EWm + (size_t)(row0+tr0+r)*512;
    #pragma unroll
    for(int g=0;g<4;g++) dr[128*g+d0] = redu(acc[r][g]) + bm[128*g+d0];
  }
  zero_acc(acc);
  gemm_pipe(acc, hA, smx, barb, d0, tr0, cg, tc);
  #pragma unroll
  for(int r=0;r<4;r++){
    float* dr = g_EWs + (size_t)(row0+tr0+r)*512;
    #pragma unroll
    for(int g=0;g<4;g++) dr[128*g+d0] = redu(acc[r][g]) + bs[128*g+d0];
  }
}

// fused pre-shuffle: 4 matrices -> k-pair-packed float2 tables.
// 32768 float2 entries per matrix -> 128 blocks x 256 threads per matrix.
__global__ void shuf_kernel(const float* __restrict__ Um, const float* __restrict__ Us,
                            const float* __restrict__ Wm, const float* __restrict__ Ws)
{
  int b=blockIdx.x, seg=b>>7;
  const float* src = (seg==0)?Um:(seg==1)?Us:(seg==2)?Wm:Ws;
  float* dst = (seg==0)?g_Ump:(seg==1)?g_Usp:(seg==2)?g_Wmp:g_Wsp;
  int i=(b&127)*256+threadIdx.x;         // 0..32767
  int kp=i>>9, col=i&511;
  ((float2*)dst)[i] = make_float2(src[(2*kp)*512+col], src[(2*kp+1)*512+col]);
}

// One-shot constants: z0 = em@Wm + bm -> c0, h0 -> z1b = h0@Um
__global__ void init_kernel(const float* __restrict__ em, const float* __restrict__ Wm,
                            const float* __restrict__ Um, const float* __restrict__ bm)
{
  __shared__ float z0[512]; __shared__ float h0[128]; __shared__ float ems[128];
  int t=threadIdx.x;
  if(t<128) ems[t]=em[t];
  __syncthreads();
  float s=bm[t];
  for(int k=0;k<128;k++) s += ems[k]*Wm[k*512+t];
  z0[t]=s;
  __syncthreads();
  if(t<128){
    float zi=z0[t], zg=z0[256+t], zo=z0[384+t];
    float c = (1.f/(1.f+expf(-zi)))*tanhf(zg);
    g_c0[t]=c;
    h0[t]=(1.f/(1.f+expf(-zo)))*tanhf(c);
  }
  __syncthreads();
  float s2=0.f;
  for(int k=0;k<128;k++) s2 += h0[k]*Um[k*512+t];
  g_z1b[t]=s2;
}

extern "C" void kernel_launch(void* const* d_in, const int* in_sizes, int n_in,
                              void* d_out, int out_size)
{
  const int*   names=(const int*)d_in[0];
  const int*   prop =(const int*)d_in[1];
  const int*   sup  =(const int*)d_in[2];
  const float* btab =(const float*)d_in[3];
  const float* Wm   =(const float*)d_in[4];
  const float* Um   =(const float*)d_in[5];
  const float* bm   =(const float*)d_in[6];
  const float* Ws   =(const float*)d_in[7];
  const float* Us   =(const float*)d_in[8];
  const float* bs   =(const float*)d_in[9];
  const float* em   =(const float*)d_in[10];
  float* emb=(float*)d_out;

  cudaFuncSetAttribute(layer_kernel,  cudaFuncAttributeMaxDynamicSharedMemorySize, SMEMB);
  cudaFuncSetAttribute(layer0_kernel, cudaFuncAttributeMaxDynamicSharedMemorySize, SMEMB);

  init_kernel<<<1,512>>>(em, Wm, Um, bm);
  shuf_kernel<<<512,256>>>(Um, Us, Wm, Ws);
  layer0_kernel<<<NBLK,NTHR,SMEMB>>>(emb, names, btab, bm, bs);
  for(int l=1;l<LLn;l++)
    layer_kernel<<<NBLK,NTHR,SMEMB>>>(l, emb,
        prop + (size_t)l*Mn*Pp, sup + (size_t)l*Mn*Ssn, bm, bs);
}

// round 13
// speedup vs baseline: 1.4979x; 1.0521x over previous
#include <cuda_runtime.h>
#include <cstddef>

#define Mn   2048
#define LLn  64
#define Pp   4
#define Ssn  2
#define RPB  16
#define NTHR 544              /* 16 consumer warps + 1 producer warp */
#define NCONS 512
#define NBLK (Mn/RPB)
#define NBUF 6
#define TILE_FLOATS 8192      /* 16 k x 512 cols x f32 = 32KB */
#define TILE_BYTES  32768

// smem floats: ring 6*8192 | hA 2048 | ids 96 | mbarriers (12 x 8B)
#define OFF_HA  49152
#define OFF_ID  51200
#define OFF_BAR 51296
#define SMEMB   (OFF_BAR*4 + 96)   /* 205280 B */

__device__ __align__(256) float g_EWm[(size_t)LLn * Mn * 512];
__device__ __align__(256) float g_EWs[(size_t)LLn * Mn * 512];
__device__ float g_c0[128];
__device__ float g_z1b[512];
// k-pair packed: [kp(64)][col(512)] float2 = {W[2kp][col], W[2kp+1][col]}
__device__ __align__(256) float g_Ump[65536];
__device__ __align__(256) float g_Usp[65536];
__device__ __align__(256) float g_Wmp[65536];
__device__ __align__(256) float g_Wsp[65536];

typedef unsigned long long u64t;

__device__ __forceinline__ float2 u2f(u64t u){ float2 v; asm("mov.b64 {%0,%1},%2;":"=f"(v.x),"=f"(v.y):"l"(u)); return v; }
__device__ __forceinline__ void fma2(u64t&a, u64t x, u64t w){ asm("fma.rn.f32x2 %0,%1,%2,%0;":"+l"(a):"l"(x),"l"(w)); }
__device__ __forceinline__ float redu(u64t a){ float2 v=u2f(a); return v.x+v.y; }

__device__ __forceinline__ unsigned smu32(const void* p){
  unsigned a; asm("{ .reg .u64 t; cvta.to.shared.u64 t, %1; cvt.u32.u64 %0, t; }":"=r"(a):"l"(p)); return a;
}
__device__ __forceinline__ void mb_init(unsigned mb, unsigned cnt){
  asm volatile("mbarrier.init.shared.b64 [%0], %1;"::"r"(mb),"r"(cnt):"memory");
}
__device__ __forceinline__ void mb_wait(unsigned mb, int ph){
  asm volatile("{\n\t.reg .pred P;\n\tWL%=:\n\tmbarrier.try_wait.parity.acquire.cta.shared::cta.b64 P, [%0], %1, 0x989680;\n\t@P bra WD%=;\n\tbra WL%=;\n\tWD%=:\n\t}"
    ::"r"(mb),"r"(ph):"memory");
}
__device__ __forceinline__ void mb_arrive(unsigned mb){
  asm volatile("mbarrier.arrive.shared.b64 _, [%0];"::"r"(mb):"memory");
}
__device__ __forceinline__ void mb_expect_tx(unsigned mb, unsigned bytes){
  asm volatile("mbarrier.arrive.expect_tx.shared.b64 _, [%0], %1;"::"r"(mb),"r"(bytes):"memory");
}
__device__ __forceinline__ void bulk_cp(unsigned dst, const float* src, unsigned bytes, unsigned mb){
  asm volatile("cp.async.bulk.shared::cta.global.mbarrier::complete_tx::bytes [%0], [%1], %2, [%3];"
    ::"r"(dst),"l"(src),"r"(bytes),"r"(mb):"memory");
}
#define CBAR()  asm volatile("bar.sync 1, %0;"::"n"(NCONS):"memory")
#define TBAR(t) asm volatile("bar.sync %0, 128;"::"r"(2+(t)):"memory")

__device__ __forceinline__ float sigf(float x){ return 1.f/(1.f+__expf(-x)); }
__device__ __forceinline__ float tfast(float x){
  x = fminf(fmaxf(x,-15.f),15.f);
  float t = __expf(2.f*x);
  return (t-1.f)/(t+1.f);
}

// ---------------- producer: stream npass*8 tiles through the 6-ring ----------------
__device__ __forceinline__ void producer(unsigned barb, unsigned smbase,
    const float* const* sched, int npass)
{
  int i=0;
  #pragma unroll 1
  for(int p=0;p<npass;p++){
    const float* W = sched[p];
    #pragma unroll 1
    for(int t=0;t<8;t++,i++){
      int s = i % NBUF;
      unsigned fb = barb + s*16;       // full barrier
      if(i >= NBUF) mb_wait(fb + 8, ((i-NBUF)/NBUF)&1);   // empty barrier
      mb_expect_tx(fb, TILE_BYTES);
      bulk_cp(smbase + s*TILE_BYTES, W + t*TILE_FLOATS, TILE_BYTES, fb);
    }
  }
}

// ---------------- consumer: one 512-col GEMM pass over 8 pipelined tiles -----------
// Thread layout: 16 warps = 4 teams x 4 warps; team=wid>>2 owns rows tr0=4*team..+3.
// Warp wsub=wid&3 covers dims [32*wsub,+32); lane cg owns dim d0=32*wsub+cg.
// Thread's 4 z-cols: gate g -> col 128*g+d0. acc[r][g]: u64 {k-even, k-odd} sums.
// NOTE: gemm reads ONLY its own team's hA rows -> intra-layer sync is per-team.
__device__ __forceinline__ void gemm_pipe(u64t acc[4][4], const float* xs,
    const float* bufbase, unsigned barb, int d0, int tr0, int cg, int& tc)
{
  #pragma unroll 1
  for(int t=0;t<8;t++){
    int s = tc % NBUF;
    unsigned fb = barb + s*16;
    mb_wait(fb, (tc/NBUF)&1);
    const u64t* wb = (const u64t*)(bufbase + s*TILE_FLOATS);
    const float* xb = xs + 16*t;
    #pragma unroll
    for(int kq=0;kq<4;kq++){
      const u64t* wA = wb + (2*kq  )*512 + d0;
      const u64t* wB = wb + (2*kq+1)*512 + d0;
      u64t a0=wA[0], a1=wA[128], a2=wA[256], a3=wA[384];
      u64t b0=wB[0], b1=wB[128], b2=wB[256], b3=wB[384];
      #pragma unroll
      for(int r=0;r<4;r++){
        ulonglong2 xv = *(const ulonglong2*)(xb + (tr0+r)*128 + 4*kq);
        fma2(acc[r][0], xv.x, a0); fma2(acc[r][1], xv.x, a1);
        fma2(acc[r][2], xv.x, a2); fma2(acc[r][3], xv.x, a3);
        fma2(acc[r][0], xv.y, b0); fma2(acc[r][1], xv.y, b1);
        fma2(acc[r][2], xv.y, b2); fma2(acc[r][3], xv.y, b3);
      }
    }
    __syncwarp();
    if(cg==0) mb_arrive(fb + 8);
    tc++;
  }
}

__device__ __forceinline__ void zero_acc(u64t acc[4][4]){
  #pragma unroll
  for(int r=0;r<4;r++)
    #pragma unroll
    for(int g=0;g<4;g++) acc[r][g]=0ull;
}

// z: i,f,g,o scalars for this thread's dim; updates c, returns h.
__device__ __forceinline__ float cell1(const float z[4], float& c){
  c = sigf(z[1])*c + sigf(z[0])*tfast(z[2]);
  return sigf(z[3])*tfast(c);
}

__global__ void __launch_bounds__(NTHR,1) layer_kernel(int l, float* __restrict__ emb,
  const int* __restrict__ prop, const int* __restrict__ sup,
  const float* __restrict__ bm, const float* __restrict__ bs)
{
  extern __shared__ float smx[];
  float* hA  = smx + OFF_HA;
  int*  ids  = (int*)(smx + OFF_ID);
  const int tid=threadIdx.x, cg=tid&31, wid=tid>>5;
  const unsigned smbase = smu32(smx);
  const unsigned barb   = smbase + OFF_BAR*4;
  const int lrow0 = blockIdx.x*RPB;
  const int base  = l*Mn + lrow0;

  if(tid==0){
    #pragma unroll
    for(int s=0;s<NBUF;s++){ mb_init(barb+s*16, 1); mb_init(barb+s*16+8, 16); }
  }
  if(tid<RPB*Pp) ids[tid] = prop[lrow0*Pp + tid];
  else if(tid<RPB*Pp+RPB*Ssn) ids[tid] = sup[lrow0*Ssn + (tid-RPB*Pp)];
  __syncthreads();

  if(wid==16){
    if(cg==0){
      const float* sched[8]={g_Ump,g_Ump,g_Ump,g_Wsp,g_Usp,g_Usp,g_Wmp,g_Wsp};
      producer(barb, smbase, sched, 8);
    }
    return;
  }

  const int team=wid>>2, wsub=wid&3;
  const int d0  = 32*wsub + cg;
  const int tr0 = 4*team;
  int tc = 0;

  u64t acc[4][4];
  float zl[4][4], zz[4][4];
  float cst[4], z[4];

  // ---- member t=1: z = E_Wm[pid0] + z1b ; c_prev = c0
  {
    float c0v = g_c0[d0];
    #pragma unroll
    for(int r=0;r<4;r++){
      const float* e = g_EWm + (size_t)ids[(tr0+r)*Pp]*512;
      #pragma unroll
      for(int g=0;g<4;g++) z[g] = e[128*g+d0] + g_z1b[128*g+d0];
      cst[r]=c0v;
      hA[(tr0+r)*128 + d0] = cell1(z, cst[r]);
    }
  }
  TBAR(team);

  // ---- member t=2..4: z = E_Wm[pid_{t-1}] + h @ Um
  #pragma unroll 1
  for(int t=2;t<=4;t++){
    zero_acc(acc);
    gemm_pipe(acc, hA, smx, barb, d0, tr0, cg, tc);
    #pragma unroll
    for(int r=0;r<4;r++){
      const float* e = g_EWm + (size_t)ids[(tr0+r)*Pp + (t-1)]*512;
      #pragma unroll
      for(int g=0;g<4;g++) zz[r][g] = redu(acc[r][g]) + e[128*g+d0];
    }
    TBAR(team);                   // team done reading its hA rows
    #pragma unroll
    for(int r=0;r<4;r++) hA[(tr0+r)*128 + d0] = cell1(zz[r], cst[r]);
    TBAR(team);                   // new h visible to team
  }
  // hA == h_m

  // ---- zl = b_s + h_m @ Ws  (x-contribution of super t=2, kept in regs)
  zero_acc(acc);
  gemm_pipe(acc, hA, smx, barb, d0, tr0, cg, tc);
  #pragma unroll
  for(int r=0;r<4;r++)
    #pragma unroll
    for(int g=0;g<4;g++) zl[r][g] = redu(acc[r][g]) + bs[128*g+d0];
  TBAR(team);                     // team done reading h_m

  // ---- super t=0: z = E_Ws[sid0], zero state
  #pragma unroll
  for(int r=0;r<4;r++){
    const float* e = g_EWs + (size_t)ids[RPB*Pp + (tr0+r)*Ssn]*512;
    #pragma unroll
    for(int g=0;g<4;g++) z[g] = e[128*g+d0];
    cst[r]=0.f;
    hA[(tr0+r)*128 + d0] = cell1(z, cst[r]);
  }
  TBAR(team);

  // ---- super t=1: z = E_Ws[sid1] + h @ Us
  zero_acc(acc);
  gemm_pipe(acc, hA, smx, barb, d0, tr0, cg, tc);
  #pragma unroll
  for(int r=0;r<4;r++){
    const float* e = g_EWs + (size_t)ids[RPB*Pp + (tr0+r)*Ssn + 1]*512;
    #pragma unroll
    for(int g=0;g<4;g++) zz[r][g] = redu(acc[r][g]) + e[128*g+d0];
  }
  TBAR(team);
  #pragma unroll
  for(int r=0;r<4;r++) hA[(tr0+r)*128 + d0] = cell1(zz[r], cst[r]);
  TBAR(team);

  // ---- super t=2: z = zl + h @ Us -> h_s
  zero_acc(acc);
  gemm_pipe(acc, hA, smx, barb, d0, tr0, cg, tc);
  #pragma unroll
  for(int r=0;r<4;r++)
    #pragma unroll
    for(int g=0;g<4;g++) zz[r][g] = redu(acc[r][g]) + zl[r][g];
  TBAR(team);
  #pragma unroll
  for(int r=0;r<4;r++) hA[(tr0+r)*128 + d0] = cell1(zz[r], cst[r]);

  // ---- write emb rows (cross-team read of hA -> one full consumer barrier)
  CBAR();
  ((float4*)(emb + (size_t)base*128))[tid] = ((const float4*)hA)[tid];

  // ---- produce z-tables for this layer's rows (gemm reads own-team hA rows only)
  zero_acc(acc);
  gemm_pipe(acc, hA, smx, barb, d0, tr0, cg, tc);
  #pragma unroll
  for(int r=0;r<4;r++){
    float* dr = g_EWm + (size_t)(base+tr0+r)*512;
    #pragma unroll
    for(int g=0;g<4;g++) dr[128*g+d0] = redu(acc[r][g]) + bm[128*g+d0];
  }
  zero_acc(acc);
  gemm_pipe(acc, hA, smx, barb, d0, tr0, cg, tc);
  #pragma unroll
  for(int r=0;r<4;r++){
    float* dr = g_EWs + (size_t)(base+tr0+r)*512;
    #pragma unroll
    for(int g=0;g<4;g++) dr[128*g+d0] = redu(acc[r][g]) + bs[128*g+d0];
  }
}

__global__ void __launch_bounds__(NTHR,1) layer0_kernel(float* __restrict__ emb,
  const int* __restrict__ names, const float* __restrict__ btab,
  const float* __restrict__ bm, const float* __restrict__ bs)
{
  extern __shared__ float smx[];
  float* hA = smx + OFF_HA;
  const int tid=threadIdx.x, cg=tid&31, wid=tid>>5;
  const unsigned smbase = smu32(smx);
  const unsigned barb   = smbase + OFF_BAR*4;
  const int row0 = blockIdx.x*RPB;

  if(tid==0){
    #pragma unroll
    for(int s=0;s<NBUF;s++){ mb_init(barb+s*16, 1); mb_init(barb+s*16+8, 16); }
  }
  for(int i=tid;i<RPB*128;i+=NTHR){
    int r=i>>7, k=i&127;
    float v = btab[names[row0+r]*128 + k];
    hA[i]=v;
    emb[(size_t)(row0+r)*128 + k]=v;
  }
  __syncthreads();

  if(wid==16){
    if(cg==0){
      const float* sched[2]={g_Wmp,g_Wsp};
      producer(barb, smbase, sched, 2);
    }
    return;
  }

  const int team=wid>>2, wsub=wid&3;
  const int d0  = 32*wsub + cg;
  const int tr0 = 4*team;
  int tc = 0;

  u64t acc[4][4];
  zero_acc(acc);
  gemm_pipe(acc, hA, smx, barb, d0, tr0, cg, tc);
  #pragma unroll
  for(int r=0;r<4;r++){
    float* dr = g_EWm + (size_t)(row0+tr0+r)*512;
    #pragma unroll
    for(int g=0;g<4;g++) dr[128*g+d0] = redu(acc[r][g]) + bm[128*g+d0];
  }
  zero_acc(acc);
  gemm_pipe(acc, hA, smx, barb, d0, tr0, cg, tc);
  #pragma unroll
  for(int r=0;r<4;r++){
    float* dr = g_EWs + (size_t)(row0+tr0+r)*512;
    #pragma unroll
    for(int g=0;g<4;g++) dr[128*g+d0] = redu(acc[r][g]) + bs[128*g+d0];
  }
}

// fused pre-shuffle: 4 matrices -> k-pair-packed float2 tables.
// 32768 float2 entries per matrix -> 128 blocks x 256 threads per matrix.
__global__ void shuf_kernel(const float* __restrict__ Um, const float* __restrict__ Us,
                            const float* __restrict__ Wm, const float* __restrict__ Ws)
{
  int b=blockIdx.x, seg=b>>7;
  const float* src = (seg==0)?Um:(seg==1)?Us:(seg==2)?Wm:Ws;
  float* dst = (seg==0)?g_Ump:(seg==1)?g_Usp:(seg==2)?g_Wmp:g_Wsp;
  int i=(b&127)*256+threadIdx.x;         // 0..32767
  int kp=i>>9, col=i&511;
  ((float2*)dst)[i] = make_float2(src[(2*kp)*512+col], src[(2*kp+1)*512+col]);
}

// One-shot constants: z0 = em@Wm + bm -> c0, h0 -> z1b = h0@Um
__global__ void init_kernel(const float* __restrict__ em, const float* __restrict__ Wm,
                            const float* __restrict__ Um, const float* __restrict__ bm)
{
  __shared__ float z0[512]; __shared__ float h0[128]; __shared__ float ems[128];
  int t=threadIdx.x;
  if(t<128) ems[t]=em[t];
  __syncthreads();
  float s=bm[t];
  for(int k=0;k<128;k++) s += ems[k]*Wm[k*512+t];
  z0[t]=s;
  __syncthreads();
  if(t<128){
    float zi=z0[t], zg=z0[256+t], zo=z0[384+t];
    float c = (1.f/(1.f+expf(-zi)))*tanhf(zg);
    g_c0[t]=c;
    h0[t]=(1.f/(1.f+expf(-zo)))*tanhf(c);
  }
  __syncthreads();
  float s2=0.f;
  for(int k=0;k<128;k++) s2 += h0[k]*Um[k*512+t];
  g_z1b[t]=s2;
}

extern "C" void kernel_launch(void* const* d_in, const int* in_sizes, int n_in,
                              void* d_out, int out_size)
{
  const int*   names=(const int*)d_in[0];
  const int*   prop =(const int*)d_in[1];
  const int*   sup  =(const int*)d_in[2];
  const float* btab =(const float*)d_in[3];
  const float* Wm   =(const float*)d_in[4];
  const float* Um   =(const float*)d_in[5];
  const float* bm   =(const float*)d_in[6];
  const float* Ws   =(const float*)d_in[7];
  const float* Us   =(const float*)d_in[8];
  const float* bs   =(const float*)d_in[9];
  const float* em   =(const float*)d_in[10];
  float* emb=(float*)d_out;

  cudaFuncSetAttribute(layer_kernel,  cudaFuncAttributeMaxDynamicSharedMemorySize, SMEMB);
  cudaFuncSetAttribute(layer0_kernel, cudaFuncAttributeMaxDynamicSharedMemorySize, SMEMB);

  init_kernel<<<1,512>>>(em, Wm, Um, bm);
  shuf_kernel<<<512,256>>>(Um, Us, Wm, Ws);
  layer0_kernel<<<NBLK,NTHR,SMEMB>>>(emb, names, btab, bm, bs);
  for(int l=1;l<LLn;l++)
    layer_kernel<<<NBLK,NTHR,SMEMB>>>(l, emb,
        prop + (size_t)l*Mn*Pp, sup + (size_t)l*Mn*Ssn, bm, bs);
}